// round 2
// baseline (speedup 1.0000x reference)
#include <cuda_runtime.h>
#include <math.h>

// Problem constants
#define B_  256
#define T_  1024
#define I_  3
#define H_  128
#define O_  3

// ---------------------------------------------------------------------------
// Packed f32x2 helpers (Blackwell sm_100+). ptxas never emits FFMA2 from C++,
// so we force it via PTX. 64-bit payload carried as unsigned long long.
// ---------------------------------------------------------------------------
typedef unsigned long long ull;

__device__ __forceinline__ ull packf2(float lo, float hi) {
    ull r;
    asm("mov.b64 %0, {%1, %2};" : "=l"(r) : "f"(lo), "f"(hi));
    return r;
}
__device__ __forceinline__ void unpackf2(ull v, float& lo, float& hi) {
    asm("mov.b64 {%0, %1}, %2;" : "=f"(lo), "=f"(hi) : "l"(v));
}
__device__ __forceinline__ ull fma2(ull a, ull b, ull c) {
    ull d;
    asm("fma.rn.f32x2 %0, %1, %2, %3;" : "=l"(d) : "l"(a), "l"(b), "l"(c));
    return d;
}
__device__ __forceinline__ ull add2(ull a, ull b) {
    ull d;
    asm("add.rn.f32x2 %0, %1, %2;" : "=l"(d) : "l"(a), "l"(b));
    return d;
}

// ---------------------------------------------------------------------------
// Recurrent kernel, f32x2 edition.
// Block = 256 threads = 2 batch elements. Grid = 128 blocks (one wave).
//   tid bits:  bs = tid>>7 (batch within block), jp = (tid>>1)&63, khalf = tid&1
// Thread computes partial sums for hidden units j0=2*jp, j1=j0+1 over
// k in [khalf*64, khalf*64+64), weights held packed {W[j0][k],W[j1][k]} in
// 128 registers. Hidden state lives duplicated in smem ({h_k,h_k} per 8B) so
// the f32x2 multiplicand is a plain LDS.128. Partner lane (tid^1, same warp)
// holds the other k-half: one shfl_xor combines. One barrier per step.
// ---------------------------------------------------------------------------
__global__ void __launch_bounds__(256, 1)
rnn_recurrent_kernel(const float* __restrict__ inputs,   // [B, T, I]
                     const float* __restrict__ W_ih,     // [H, I]
                     const float* __restrict__ W_hh,     // [H, H]
                     const float* __restrict__ b_ih,     // [H]
                     const float* __restrict__ b_hh,     // [H]
                     const float* __restrict__ h0,       // [1, H]
                     float* __restrict__ hiddens)        // [B, T, H]
{
    const int tid   = threadIdx.x;
    const int bs    = tid >> 7;          // 0/1: batch within block
    const int jp    = (tid >> 1) & 63;   // hidden-unit pair index
    const int khalf = tid & 1;           // which half of the K sum
    const int j0    = 2 * jp;
    const int j1    = j0 + 1;
    const int kbase = khalf * 64;
    const int bb    = 2 * blockIdx.x + bs;

    // Duplicated hidden state: hbuf[buf][bs][k] = {h_k, h_k}
    __shared__ ull hbuf[2][2][H_];

    // Packed W_hh rows: w2[kk] = {W_hh[j0][kbase+kk], W_hh[j1][kbase+kk]}
    ull w2[64];
    {
        const float* r0 = W_hh + j0 * H_ + kbase;
        const float* r1 = W_hh + j1 * H_ + kbase;
#pragma unroll
        for (int kk = 0; kk < 64; ++kk)
            w2[kk] = packf2(r0[kk], r1[kk]);
    }

    // Packed input-proj weights and bias for (j0, j1)
    const ull wp0   = packf2(W_ih[j0 * I_ + 0], W_ih[j1 * I_ + 0]);
    const ull wp1   = packf2(W_ih[j0 * I_ + 1], W_ih[j1 * I_ + 1]);
    const ull wp2   = packf2(W_ih[j0 * I_ + 2], W_ih[j1 * I_ + 2]);
    const ull bias2 = packf2(b_ih[j0] + b_hh[j0], b_ih[j1] + b_hh[j1]);

    // Init hidden state (duplicated) for both batches of this block
    {
        const int k  = tid & 127;
        const int b2 = tid >> 7;
        const float v = h0[k];
        hbuf[0][b2][k] = packf2(v, v);
    }
    __syncthreads();

    const float* inb  = inputs + (size_t)bb * T_ * I_;
    float*       hout = hiddens + (size_t)bb * T_ * H_;

    int cur = 0;
#pragma unroll 1
    for (int t = 0; t < T_; ++t) {
        // Input projection for (j0, j1), packed
        const float x0 = __ldg(inb + t * I_ + 0);
        const float x1 = __ldg(inb + t * I_ + 1);
        const float x2 = __ldg(inb + t * I_ + 2);
        ull xp = fma2(packf2(x0, x0), wp0,
                 fma2(packf2(x1, x1), wp1,
                 fma2(packf2(x2, x2), wp2, bias2)));

        // Partial h . W_hh over this thread's k-half: 32 FFMA2 x 4 chains
        ull a0 = 0ull, a1 = 0ull, a2 = 0ull, a3 = 0ull;
        const ulonglong2* hp = reinterpret_cast<const ulonglong2*>(&hbuf[cur][bs][kbase]);
#pragma unroll
        for (int kk = 0; kk < 16; ++kk) {
            ulonglong2 hva = hp[2 * kk + 0];
            ulonglong2 hvb = hp[2 * kk + 1];
            a0 = fma2(hva.x, w2[4 * kk + 0], a0);
            a1 = fma2(hva.y, w2[4 * kk + 1], a1);
            a2 = fma2(hvb.x, w2[4 * kk + 2], a2);
            a3 = fma2(hvb.y, w2[4 * kk + 3], a3);
        }
        ull s = add2(add2(a0, a1), add2(a2, a3));

        // Combine the two k-halves (partner lane = tid^1, same warp)
        s = add2(s, __shfl_xor_sync(0xffffffffu, s, 1));
        s = add2(s, xp);

        float f0, f1;
        unpackf2(s, f0, f1);
        const float t0 = tanhf(f0);
        const float t1 = tanhf(f1);

        const int nxt = cur ^ 1;
        if (khalf == 0) {
            // duplicated smem store: {t0,t0,t1,t1} = 16B at [j0]
            ulonglong2 v;
            v.x = packf2(t0, t0);
            v.y = packf2(t1, t1);
            *reinterpret_cast<ulonglong2*>(&hbuf[nxt][bs][j0]) = v;
        } else {
            // coalesced global store of hiddens
            float2 g;
            g.x = t0; g.y = t1;
            *reinterpret_cast<float2*>(hout + t * H_ + j0) = g;
        }
        cur = nxt;
        __syncthreads();
    }
}

// ---------------------------------------------------------------------------
// Output projection: 4 rows per warp to amortize W_out loads and raise MLP.
// ---------------------------------------------------------------------------
#define ROWS_PER_WARP 4

__global__ void rnn_outproj_kernel(const float* __restrict__ hiddens, // [B*T, H]
                                   const float* __restrict__ W_out,   // [O, H]
                                   const float* __restrict__ b_out,   // [O]
                                   float* __restrict__ out)           // [B*T, O]
{
    const int warp = (blockIdx.x * blockDim.x + threadIdx.x) >> 5;
    const int lane = threadIdx.x & 31;
    const int row0 = warp * ROWS_PER_WARP;
    if (row0 >= B_ * T_) return;

    const float4 w0 = reinterpret_cast<const float4*>(W_out + 0 * H_)[lane];
    const float4 w1 = reinterpret_cast<const float4*>(W_out + 1 * H_)[lane];
    const float4 w2 = reinterpret_cast<const float4*>(W_out + 2 * H_)[lane];
    const float bo0 = b_out[0], bo1 = b_out[1], bo2 = b_out[2];

    // Issue all 4 row loads up front (MLP)
    float4 hv[ROWS_PER_WARP];
#pragma unroll
    for (int r = 0; r < ROWS_PER_WARP; ++r)
        hv[r] = reinterpret_cast<const float4*>(hiddens + (size_t)(row0 + r) * H_)[lane];

#pragma unroll
    for (int r = 0; r < ROWS_PER_WARP; ++r) {
        float s0 = hv[r].x * w0.x + hv[r].y * w0.y + hv[r].z * w0.z + hv[r].w * w0.w;
        float s1 = hv[r].x * w1.x + hv[r].y * w1.y + hv[r].z * w1.z + hv[r].w * w1.w;
        float s2 = hv[r].x * w2.x + hv[r].y * w2.y + hv[r].z * w2.z + hv[r].w * w2.w;
#pragma unroll
        for (int off = 16; off > 0; off >>= 1) {
            s0 += __shfl_down_sync(0xffffffffu, s0, off);
            s1 += __shfl_down_sync(0xffffffffu, s1, off);
            s2 += __shfl_down_sync(0xffffffffu, s2, off);
        }
        if (lane == 0) {
            float* o = out + (size_t)(row0 + r) * O_;
            o[0] = s0 + bo0;
            o[1] = s1 + bo1;
            o[2] = s2 + bo2;
        }
    }
}

// ---------------------------------------------------------------------------
// kernel_launch
// ---------------------------------------------------------------------------
extern "C" void kernel_launch(void* const* d_in, const int* in_sizes, int n_in,
                              void* d_out, int out_size)
{
    const float* inputs = (const float*)d_in[0];
    const float* W_ih   = (const float*)d_in[1];
    const float* W_hh   = (const float*)d_in[2];
    const float* b_ih   = (const float*)d_in[3];
    const float* b_hh   = (const float*)d_in[4];
    const float* h0     = (const float*)d_in[5];
    const float* W_out  = (const float*)d_in[6];
    const float* b_out  = (const float*)d_in[7];

    float* out     = (float*)d_out;                        // [B,T,O]
    float* hiddens = (float*)d_out + (size_t)B_ * T_ * O_; // [B,T,H]

    rnn_recurrent_kernel<<<B_ / 2, 256>>>(inputs, W_ih, W_hh, b_ih, b_hh, h0, hiddens);

    const int rows  = B_ * T_;
    const int warps_per_block = 256 / 32;
    const int rows_per_block  = warps_per_block * ROWS_PER_WARP;
    const int blocks = (rows + rows_per_block - 1) / rows_per_block;
    rnn_outproj_kernel<<<blocks, 256>>>(hiddens, W_out, b_out, out);
}

// round 3
// speedup vs baseline: 1.7940x; 1.7940x over previous
#include <cuda_runtime.h>
#include <math.h>

// Problem constants
#define B_  256
#define T_  1024
#define I_  3
#define H_  128
#define O_  3

// ---------------------------------------------------------------------------
// Fast tanh: sign(x) * (1 - e) / (1 + e),  e = 2^(-2*log2(e)*|x|) = exp(-2|x|)
// ex2.approx (~2 ulp) + rcp.approx (~1 ulp) -> rel err ~1e-6, chain ~48 cyc.
// Large |x|: e -> 0 -> result -> ±1 (correct saturation). x=0 -> 0.
// ---------------------------------------------------------------------------
__device__ __forceinline__ float fast_tanh(float x) {
    const float ax = fabsf(x);
    float e;
    asm("ex2.approx.f32 %0, %1;" : "=f"(e) : "f"(ax * -2.885390081777927f));
    float rd;
    asm("rcp.approx.f32 %0, %1;" : "=f"(rd) : "f"(1.0f + e));
    return copysignf((1.0f - e) * rd, x);
}

// ---------------------------------------------------------------------------
// Recurrent kernel: one block per batch element, one thread per hidden unit.
// Thread j keeps W_hh row j in 128 registers. Hidden state in smem,
// double-buffered -> one barrier per step. Input projection fused; x for the
// next step prefetched before the K-loop so its LDG latency overlaps FFMAs.
// ---------------------------------------------------------------------------
__global__ void __launch_bounds__(H_, 2)
rnn_recurrent_kernel(const float* __restrict__ inputs,   // [B, T, I]
                     const float* __restrict__ W_ih,     // [H, I]
                     const float* __restrict__ W_hh,     // [H, H]
                     const float* __restrict__ b_ih,     // [H]
                     const float* __restrict__ b_hh,     // [H]
                     const float* __restrict__ h0,       // [1, H]
                     float* __restrict__ hiddens)        // [B, T, H]
{
    const int b = blockIdx.x;
    const int j = threadIdx.x;

    __shared__ float hbuf[2][H_];

    // W_hh row j -> registers
    float w[H_];
    const float4* wrow = reinterpret_cast<const float4*>(W_hh + j * H_);
#pragma unroll
    for (int kk = 0; kk < H_ / 4; ++kk) {
        float4 v = wrow[kk];
        w[4 * kk + 0] = v.x;
        w[4 * kk + 1] = v.y;
        w[4 * kk + 2] = v.z;
        w[4 * kk + 3] = v.w;
    }

    const float wi0  = W_ih[j * I_ + 0];
    const float wi1  = W_ih[j * I_ + 1];
    const float wi2  = W_ih[j * I_ + 2];
    const float bias = b_ih[j] + b_hh[j];

    hbuf[0][j] = h0[j];
    __syncthreads();

    const float* inb  = inputs + (size_t)b * T_ * I_;
    float*       hout = hiddens + (size_t)b * T_ * H_;

    // Prime the input pipeline
    float x0 = inb[0], x1 = inb[1], x2 = inb[2];

    int cur = 0;
#pragma unroll 1
    for (int t = 0; t < T_; ++t) {
        // Input projection with already-loaded x (not in the critical tail)
        float acc = fmaf(x0, wi0, fmaf(x1, wi1, fmaf(x2, wi2, bias)));

        // Prefetch next step's x (clamped index avoids OOB; predicated loads)
        {
            const int tn = (t + 1 < T_) ? (t + 1) : (T_ - 1);
            const float* nx = inb + tn * I_;
            x0 = nx[0]; x1 = nx[1]; x2 = nx[2];
        }

        // h . W_hh[j,:] — broadcast smem reads, 4 independent FMA chains
        float a0 = 0.f, a1 = 0.f, a2 = 0.f, a3 = 0.f;
        const float4* h4 = reinterpret_cast<const float4*>(hbuf[cur]);
#pragma unroll
        for (int kk = 0; kk < H_ / 4; ++kk) {
            float4 hv = h4[kk];
            a0 = fmaf(hv.x, w[4 * kk + 0], a0);
            a1 = fmaf(hv.y, w[4 * kk + 1], a1);
            a2 = fmaf(hv.z, w[4 * kk + 2], a2);
            a3 = fmaf(hv.w, w[4 * kk + 3], a3);
        }
        acc += (a0 + a1) + (a2 + a3);

        const float hn = fast_tanh(acc);
        const int nxt = cur ^ 1;
        hbuf[nxt][j] = hn;           // other buffer: no WAR on readers
        hout[t * H_ + j] = hn;       // coalesced, fire-and-forget
        cur = nxt;
        __syncthreads();
    }
}

// ---------------------------------------------------------------------------
// Output projection: 8 rows per warp (MLP=8, W_out register reuse).
// ---------------------------------------------------------------------------
#define ROWS_PER_WARP 8

__global__ void __launch_bounds__(256)
rnn_outproj_kernel(const float* __restrict__ hiddens, // [B*T, H]
                   const float* __restrict__ W_out,   // [O, H]
                   const float* __restrict__ b_out,   // [O]
                   float* __restrict__ out)           // [B*T, O]
{
    const int warp = (blockIdx.x * blockDim.x + threadIdx.x) >> 5;
    const int lane = threadIdx.x & 31;
    const int row0 = warp * ROWS_PER_WARP;
    if (row0 >= B_ * T_) return;

    const float4 w0 = reinterpret_cast<const float4*>(W_out + 0 * H_)[lane];
    const float4 w1 = reinterpret_cast<const float4*>(W_out + 1 * H_)[lane];
    const float4 w2 = reinterpret_cast<const float4*>(W_out + 2 * H_)[lane];
    const float bo0 = b_out[0], bo1 = b_out[1], bo2 = b_out[2];

    // Issue all row loads up front (MLP)
    float4 hv[ROWS_PER_WARP];
#pragma unroll
    for (int r = 0; r < ROWS_PER_WARP; ++r)
        hv[r] = reinterpret_cast<const float4*>(hiddens + (size_t)(row0 + r) * H_)[lane];

#pragma unroll
    for (int r = 0; r < ROWS_PER_WARP; ++r) {
        float s0 = hv[r].x * w0.x + hv[r].y * w0.y + hv[r].z * w0.z + hv[r].w * w0.w;
        float s1 = hv[r].x * w1.x + hv[r].y * w1.y + hv[r].z * w1.z + hv[r].w * w1.w;
        float s2 = hv[r].x * w2.x + hv[r].y * w2.y + hv[r].z * w2.z + hv[r].w * w2.w;
#pragma unroll
        for (int off = 16; off > 0; off >>= 1) {
            s0 += __shfl_down_sync(0xffffffffu, s0, off);
            s1 += __shfl_down_sync(0xffffffffu, s1, off);
            s2 += __shfl_down_sync(0xffffffffu, s2, off);
        }
        if (lane == 0) {
            float* o = out + (size_t)(row0 + r) * O_;
            o[0] = s0 + bo0;
            o[1] = s1 + bo1;
            o[2] = s2 + bo2;
        }
    }
}

// ---------------------------------------------------------------------------
// kernel_launch
// ---------------------------------------------------------------------------
extern "C" void kernel_launch(void* const* d_in, const int* in_sizes, int n_in,
                              void* d_out, int out_size)
{
    const float* inputs = (const float*)d_in[0];
    const float* W_ih   = (const float*)d_in[1];
    const float* W_hh   = (const float*)d_in[2];
    const float* b_ih   = (const float*)d_in[3];
    const float* b_hh   = (const float*)d_in[4];
    const float* h0     = (const float*)d_in[5];
    const float* W_out  = (const float*)d_in[6];
    const float* b_out  = (const float*)d_in[7];

    float* out     = (float*)d_out;                        // [B,T,O]
    float* hiddens = (float*)d_out + (size_t)B_ * T_ * O_; // [B,T,H]

    rnn_recurrent_kernel<<<B_, H_>>>(inputs, W_ih, W_hh, b_ih, b_hh, h0, hiddens);

    const int rows = B_ * T_;
    const int rows_per_block = (256 / 32) * ROWS_PER_WARP;
    const int blocks = (rows + rows_per_block - 1) / rows_per_block;
    rnn_outproj_kernel<<<blocks, 256>>>(hiddens, W_out, b_out, out);
}